// round 3
// baseline (speedup 1.0000x reference)
#include <cuda_runtime.h>
#include <math.h>

// ---------------- problem constants ----------------
#define BATCHN 8
#define TLEN   1024
#define DM     512          // D_MODEL
#define HH     1024         // H per direction
#define K3H    3072         // 3*H
#define NWALL  6144         // 2*3H  (both directions)
#define NTOK   8192         // B*T
#define GOUT   2048         // GRU_OUT
#define FFND   2048
#define NE     8
#define GRU_CTAS 128

// ---------------- static device scratch ----------------
__device__ float g_xg[(size_t)NTOK * NWALL];      // x@Wih^T + bih, [token][dir*3H+row]
__device__ float g_wT[(size_t)DM * NWALL];        // Wih transposed: [K=512][N=6144]
__device__ float g_flat[(size_t)NTOK * GOUT];     // leaky_relu(gru_out)
__device__ float g_h1[(size_t)NTOK * 2 * FFND];   // gelu(flat@W1+b1) per assignment row
__device__ float g_obuf[(size_t)NTOK * 2 * DM];   // per-assignment expert outputs
__device__ float g_hbuf[2][2][BATCHN][HH];        // ping-pong hidden state
__device__ int   g_list[NE][NTOK];                // per-expert assignment list (token*2+k)
__device__ int   g_cnt[NE];
__device__ float g_wt[NTOK * 2];                  // normalized top-2 weights
__device__ float g_Psum[NE];
__device__ float g_zsum;
// software grid barrier
__device__ unsigned g_barcnt;
__device__ volatile unsigned g_bargen;

// ---------------- init ----------------
__global__ void init_kernel() {
    int i = blockIdx.x * blockDim.x + threadIdx.x;
    float* h0 = &g_hbuf[0][0][0][0];
    if (i < 2 * BATCHN * HH) h0[i] = 0.f;
    float* h1 = &g_hbuf[1][0][0][0];
    if (i < 2 * BATCHN * HH) h1[i] = 0.f;
    if (i < NE) { g_cnt[i] = 0; g_Psum[i] = 0.f; }
    if (i == 0) { g_zsum = 0.f; g_barcnt = 0u; g_bargen = 0u; }
}

// ---------------- transpose Wih [6144][512] -> g_wT [512][6144] ----------------
__global__ void transpose_w(const float* __restrict__ W) {
    __shared__ float tile[32][33];
    int k0 = blockIdx.x * 32, n0 = blockIdx.y * 32;
    int tx = threadIdx.x, ty = threadIdx.y;            // 32 x 8
    #pragma unroll
    for (int r = 0; r < 32; r += 8)
        tile[ty + r][tx] = W[(size_t)(n0 + ty + r) * DM + k0 + tx];
    __syncthreads();
    #pragma unroll
    for (int r = 0; r < 32; r += 8)
        g_wT[(size_t)(k0 + ty + r) * NWALL + n0 + tx] = tile[tx][ty + r];
}

// ---------------- generic 128x128x8 SGEMM (NN), optional gather + gelu ----------------
__global__ void __launch_bounds__(256) gemm128(
    const float* __restrict__ A, int lda,
    const float* __restrict__ B, int ldb,
    const float* __restrict__ bias, int biasPerExp,
    float* __restrict__ C, int ldc,
    int M, int N, int K,
    int useList, int aDiv, int act, long bStride)
{
    const int* glist = nullptr;
    if (useList) {
        int e = blockIdx.z;
        M = g_cnt[e];
        glist = g_list[e];
        B += bStride * e;
        bias += (size_t)biasPerExp * e;
    }
    int m0 = blockIdx.y * 128;
    if (m0 >= M) return;
    int n0 = blockIdx.x * 128;

    __shared__ float As[8][128];
    __shared__ float Bs[8][128];

    int tid = threadIdx.x;
    int tx = tid & 15, ty = tid >> 4;
    int la_r = tid >> 1;            // A tile row (0..127)
    int la_k = (tid & 1) << 2;      // A tile k-offset (0 or 4)

    int mA = m0 + la_r;
    bool aValid = (mA < M);
    size_t arow = 0;
    if (aValid) {
        if (glist) { int gv = glist[mA]; arow = (size_t)(aDiv ? (gv >> 1) : gv); }
        else       arow = (size_t)mA;
    }
    const float* Aptr = A + arow * (size_t)lda + la_k;
    const float* Bptr = B + (size_t)(tid >> 5) * ldb + n0 + ((tid & 31) << 2);

    float acc[8][8];
    #pragma unroll
    for (int i = 0; i < 8; i++)
        #pragma unroll
        for (int j = 0; j < 8; j++) acc[i][j] = 0.f;

    for (int k0 = 0; k0 < K; k0 += 8) {
        float4 av = aValid ? *(const float4*)Aptr : make_float4(0.f, 0.f, 0.f, 0.f);
        As[la_k + 0][la_r] = av.x; As[la_k + 1][la_r] = av.y;
        As[la_k + 2][la_r] = av.z; As[la_k + 3][la_r] = av.w;
        *(float4*)&Bs[tid >> 5][(tid & 31) << 2] = *(const float4*)Bptr;
        __syncthreads();
        #pragma unroll
        for (int kk = 0; kk < 8; kk++) {
            float ra[8], rb[8];
            *(float4*)&ra[0] = *(const float4*)&As[kk][ty * 8];
            *(float4*)&ra[4] = *(const float4*)&As[kk][ty * 8 + 4];
            *(float4*)&rb[0] = *(const float4*)&Bs[kk][tx * 8];
            *(float4*)&rb[4] = *(const float4*)&Bs[kk][tx * 8 + 4];
            #pragma unroll
            for (int i = 0; i < 8; i++)
                #pragma unroll
                for (int j = 0; j < 8; j++)
                    acc[i][j] = fmaf(ra[i], rb[j], acc[i][j]);
        }
        __syncthreads();
        Aptr += 8;
        Bptr += (size_t)8 * ldb;
    }

    float bv[8];
    #pragma unroll
    for (int j = 0; j < 8; j++) bv[j] = bias[n0 + tx * 8 + j];

    #pragma unroll
    for (int i = 0; i < 8; i++) {
        int m = m0 + ty * 8 + i;
        if (m >= M) break;
        size_t crow = glist ? (size_t)glist[m] : (size_t)m;
        float* Cp = C + crow * (size_t)ldc + n0 + tx * 8;
        float v[8];
        #pragma unroll
        for (int j = 0; j < 8; j++) {
            float t = acc[i][j] + bv[j];
            if (act) t = 0.5f * t * (1.0f + erff(t * 0.70710678118654752f));
            v[j] = t;
        }
        *(float4*)Cp       = *(float4*)&v[0];
        *(float4*)(Cp + 4) = *(float4*)&v[4];
    }
}

// ---------------- software grid barrier (all CTAs co-resident) ----------------
__device__ __forceinline__ void grid_sync() {
    __syncthreads();
    if (threadIdx.x == 0) {
        __threadfence();
        unsigned gen = g_bargen;
        if (atomicAdd(&g_barcnt, 1u) == GRU_CTAS - 1) {
            g_barcnt = 0;
            __threadfence();
            g_bargen = gen + 1;
        } else {
            while (g_bargen == gen) __nanosleep(64);
        }
    }
    __syncthreads();
}

// ---------------- persistent bidirectional GRU ----------------
// 128 CTAs x 512 threads, one wave (<=148 SMs). Warp = one hidden unit j of one
// direction; 3 recurrent dot products over all 8 batches per step.
__global__ void __launch_bounds__(512) gru_persist(
    const float* __restrict__ Whh, const float* __restrict__ bhh)
{
    __shared__ float hs[BATCHN * HH];   // 32 KB previous hidden state (this dir)
    int bx = blockIdx.x;                // 0..127
    int dir = bx >> 6;
    int warp = threadIdx.x >> 5;        // 0..15
    int lane = threadIdx.x & 31;
    int j = (bx & 63) * 16 + warp;      // 0..1023

    const float* W0  = Whh + (size_t)dir * K3H * HH + (size_t)j * HH;
    const float* W1p = W0 + (size_t)HH * HH;
    const float* W2p = W0 + (size_t)2 * HH * HH;
    const float* bh  = bhh + dir * K3H;
    float bh_r = bh[j], bh_z = bh[HH + j], bh_n = bh[2 * HH + j];

    for (int s = 0; s < TLEN; s++) {
        int t = dir ? (TLEN - 1 - s) : s;
        const float* hprev = &g_hbuf[s & 1][dir][0][0];
        for (int idx = threadIdx.x; idx < BATCHN * HH; idx += 512)
            hs[idx] = __ldcg(&hprev[idx]);      // bypass L1 (stale-line hazard)
        __syncthreads();

        float a0[8], a1[8], a2[8];
        #pragma unroll
        for (int b = 0; b < 8; b++) { a0[b] = 0.f; a1[b] = 0.f; a2[b] = 0.f; }

        for (int i = 0; i < 32; i++) {
            int k = lane + (i << 5);
            float w0 = W0[k], w1 = W1p[k], w2 = W2p[k];
            #pragma unroll
            for (int b = 0; b < 8; b++) {
                float hv = hs[b * HH + k];
                a0[b] = fmaf(w0, hv, a0[b]);
                a1[b] = fmaf(w1, hv, a1[b]);
                a2[b] = fmaf(w2, hv, a2[b]);
            }
        }
        #pragma unroll
        for (int b = 0; b < 8; b++) {
            #pragma unroll
            for (int off = 16; off > 0; off >>= 1) {
                a0[b] += __shfl_xor_sync(0xffffffffu, a0[b], off);
                a1[b] += __shfl_xor_sync(0xffffffffu, a1[b], off);
                a2[b] += __shfl_xor_sync(0xffffffffu, a2[b], off);
            }
        }

        if (lane < 8) {
            int b = lane;
            int token = b * TLEN + t;
            const float* xgr = g_xg + (size_t)token * NWALL + (size_t)dir * K3H;
            float xr = xgr[j], xz = xgr[HH + j], xn = xgr[2 * HH + j];
            float hr = a0[b] + bh_r;
            float hz = a1[b] + bh_z;
            float hn = a2[b] + bh_n;
            float r  = 1.f / (1.f + expf(-(xr + hr)));
            float z  = 1.f / (1.f + expf(-(xz + hz)));
            float nn = tanhf(xn + r * hn);
            float hp = hs[b * HH + j];
            float hnew = (1.f - z) * nn + z * hp;
            g_hbuf[(s + 1) & 1][dir][b][j] = hnew;
            g_flat[(size_t)token * GOUT + dir * HH + j] =
                hnew > 0.f ? hnew : 0.01f * hnew;
        }
        grid_sync();
    }
}

// ---------------- gating: warp per token ----------------
__global__ void gate_kernel(const float* __restrict__ gW, const float* __restrict__ gb) {
    int gwid = (blockIdx.x * blockDim.x + threadIdx.x) >> 5;
    int lane = threadIdx.x & 31;
    if (gwid >= NTOK) return;
    const float* f = g_flat + (size_t)gwid * GOUT;
    float acc[NE];
    #pragma unroll
    for (int e = 0; e < NE; e++) acc[e] = 0.f;
    for (int k = lane; k < GOUT; k += 32) {
        float fv = f[k];
        #pragma unroll
        for (int e = 0; e < NE; e++) acc[e] = fmaf(fv, gW[e * GOUT + k], acc[e]);
    }
    #pragma unroll
    for (int e = 0; e < NE; e++)
        #pragma unroll
        for (int off = 16; off > 0; off >>= 1)
            acc[e] += __shfl_xor_sync(0xffffffffu, acc[e], off);

    if (lane == 0) {
        float l[NE], mx = -1e30f;
        #pragma unroll
        for (int e = 0; e < NE; e++) { l[e] = acc[e] + gb[e]; mx = fmaxf(mx, l[e]); }
        float se = 0.f;
        #pragma unroll
        for (int e = 0; e < NE; e++) se += expf(l[e] - mx);
        float lse = mx + logf(se);
        float sc[NE];
        #pragma unroll
        for (int e = 0; e < NE; e++) sc[e] = expf(l[e] - lse);
        int e0 = 0; float s0 = sc[0];
        #pragma unroll
        for (int e = 1; e < NE; e++) if (sc[e] > s0) { s0 = sc[e]; e0 = e; }
        int e1 = -1; float s1 = -1e30f;
        #pragma unroll
        for (int e = 0; e < NE; e++) if (e != e0 && sc[e] > s1) { s1 = sc[e]; e1 = e; }
        float inv = 1.f / (s0 + s1);
        int p0 = atomicAdd(&g_cnt[e0], 1);
        g_list[e0][p0] = gwid * 2;
        int p1 = atomicAdd(&g_cnt[e1], 1);
        g_list[e1][p1] = gwid * 2 + 1;
        g_wt[gwid * 2]     = s0 * inv;
        g_wt[gwid * 2 + 1] = s1 * inv;
        atomicAdd(&g_zsum, lse * lse);
        #pragma unroll
        for (int e = 0; e < NE; e++) atomicAdd(&g_Psum[e], sc[e]);
    }
}

// ---------------- deterministic combine ----------------
__global__ void combine_kernel(float* __restrict__ out) {
    int idx = blockIdx.x * blockDim.x + threadIdx.x;
    if (idx >= NTOK * DM) return;
    int t = idx >> 9;
    int d = idx & (DM - 1);
    out[idx] = g_wt[2 * t]     * g_obuf[(size_t)(2 * t) * DM + d]
             + g_wt[2 * t + 1] * g_obuf[(size_t)(2 * t + 1) * DM + d];
}

// ---------------- aux loss scalar ----------------
__global__ void aux_kernel(float* out, int out_size) {
    if (out_size <= NTOK * DM) return;
    float s = 0.f;
    #pragma unroll
    for (int e = 0; e < NE; e++)
        s += ((float)g_cnt[e] / (float)NTOK) * (g_Psum[e] / (float)NTOK);
    out[NTOK * DM] = 0.01f * (float)NE * s + 0.001f * (g_zsum / (float)NTOK);
}

// ---------------- launch ----------------
extern "C" void kernel_launch(void* const* d_in, const int* in_sizes, int n_in,
                              void* d_out, int out_size) {
    const float* x   = (const float*)d_in[0];
    const float* Wih = (const float*)d_in[1];
    const float* Whh = (const float*)d_in[2];
    const float* bih = (const float*)d_in[3];
    const float* bhh = (const float*)d_in[4];
    const float* gW  = (const float*)d_in[5];
    const float* gb  = (const float*)d_in[6];
    const float* W1  = (const float*)d_in[7];
    const float* b1  = (const float*)d_in[8];
    const float* W2  = (const float*)d_in[9];
    const float* b2  = (const float*)d_in[10];
    float* out = (float*)d_out;

    float *p_xg, *p_flat, *p_h1, *p_obuf, *p_wT;
    cudaGetSymbolAddress((void**)&p_xg,   g_xg);
    cudaGetSymbolAddress((void**)&p_flat, g_flat);
    cudaGetSymbolAddress((void**)&p_h1,   g_h1);
    cudaGetSymbolAddress((void**)&p_obuf, g_obuf);
    cudaGetSymbolAddress((void**)&p_wT,   g_wT);

    init_kernel<<<64, 256>>>();
    transpose_w<<<dim3(16, 192), dim3(32, 8)>>>(Wih);

    // xg = x @ Wih^T + bih : M=8192, N=6144, K=512
    gemm128<<<dim3(48, 64, 1), 256>>>(x, DM, p_wT, NWALL, bih, 0,
                                      p_xg, NWALL, NTOK, NWALL, DM,
                                      0, 0, 0, 0L);

    // bidirectional GRU: one persistent kernel, software grid barrier per step
    gru_persist<<<GRU_CTAS, 512>>>(Whh, bhh);

    gate_kernel<<<NTOK / 8, 256>>>(gW, gb);

    // expert GEMM1 + GELU (gathered rows of flat)
    gemm128<<<dim3(16, 64, 8), 256>>>(p_flat, GOUT, W1, FFND, b1, FFND,
                                      p_h1, FFND, 0, FFND, GOUT,
                                      1, 1, 1, (long)GOUT * FFND);
    // expert GEMM2
    gemm128<<<dim3(4, 64, 8), 256>>>(p_h1, FFND, W2, DM, b2, DM,
                                     p_obuf, DM, 0, DM, FFND,
                                     1, 0, 0, (long)FFND * DM);

    combine_kernel<<<(NTOK * DM + 255) / 256, 256>>>(out);
    aux_kernel<<<1, 1>>>(out, out_size);
}